// round 15
// baseline (speedup 1.0000x reference)
#include <cuda_runtime.h>
#include <math.h>

#define Bb 2
#define Hh 64
#define Ww 64
#define LL 4096
#define Cc 96
#define Ee 192
#define Nn 16
#define CATC 768

static __device__ float g_x2d  [Bb*Cc*LL];
static __device__ float g_cat  [Bb*CATC*LL];
static __device__ __align__(16) float g_fpart[4*Bb*Cc*LL];
static __device__ float g_xpT  [Bb*Ee*LL];
static __device__ float g_zp   [Bb*LL*Ee];
static __device__ float g_delta[Bb*Ee*LL];        // [B,E,L]
static __device__ __align__(8) float2 g_BC[Bb*LL*Nn];   // (B,C) pairs
static __device__ __align__(8) int2   g_ordp[2*LL];     // (ord[2p], ord[2p+1])
static __device__ __align__(16) float g_yd[Bb*LL*Ee*4];   // [B,L,E,4dirs]
static __device__ float g_clC  [Bb*Cc*LL];
static __device__ float g_cl   [Bb*LL*Ee];
static __device__ __align__(16) float2 g_WtIn2 [Cc*2*Ee]; // dup (w,w)
static __device__ __align__(16) float2 g_WtCl2 [Cc*Ee];
static __device__ __align__(8)  float2 g_WtOut2[Ee*Cc];
static __device__ __align__(16) float2 g_fw2   [CATC*Cc]; // fuse weights dup: [c][o]

__device__ __forceinline__ float siluf(float v){ return v / (1.f + __expf(-v)); }

__device__ __forceinline__ unsigned long long pack2(float x, float y){
  unsigned long long d;
  asm("mov.b64 %0, {%1, %2};" : "=l"(d) : "f"(x), "f"(y));
  return d;
}
__device__ __forceinline__ unsigned long long ffma2(unsigned long long a, unsigned long long b, unsigned long long c){
  unsigned long long d;
  asm("fma.rn.f32x2 %0, %1, %2, %3;" : "=l"(d) : "l"(a), "l"(b), "l"(c));
  return d;
}
__device__ __forceinline__ void unpack2(unsigned long long d, float& x, float& y){
  asm("mov.b64 {%0, %1}, %2;" : "=f"(x), "=f"(y) : "l"(d));
}

// ---------------- prep: orders + duplicated weight transposes --------------
__global__ void k_prep(const float* __restrict__ inw, const float* __restrict__ clw,
                       const float* __restrict__ opw, const float* __restrict__ fwm){
  int idx = blockIdx.x*256 + threadIdx.x;
  if (idx < 36864){
    int j = idx/96, c = idx%96;
    float w = inw[idx];
    g_WtIn2[c*384 + j] = make_float2(w, w);
  } else if (idx < 36864+18432){
    int r = idx - 36864;
    int e = r/96, c = r%96;
    float w = clw[r];
    g_WtCl2[c*192 + e] = make_float2(w, w);
  } else if (idx < 73728){
    int r = idx - 36864 - 18432;
    int o = r/192, e = r%192;
    float w = opw[r];
    g_WtOut2[e*96 + o] = make_float2(w, w);
  } else if (idx < 73728 + 73728){
    int r = idx - 73728;
    int o = r/768, c = r%768;
    float w = fwm[r];
    g_fw2[c*96 + o] = make_float2(w, w);
  }
  int l = idx - 147456;
  if (l >= 0 && l < LL){
    int r = l >> 6, k = l & 63;
    int i = Hh-1-r;
    int j = (r & 1) ? (Ww-1-k) : k;
    int o1 = i*Ww + j;
    int c = l >> 6, tt = l & 63;
    int i2 = (c & 1) ? (Hh-1-tt) : tt;
    g_ordp[l] = make_int2(o1, i2*Ww + c);
  }
  if (l >= 0 && l < Hh+Ww-1){
    int d = l;
    int off = (d < 64) ? d*(d+1)/2 : 2080 + (d-64)*(191-d)/2;
    int i0 = (d > 63) ? d-63 : 0;
    int i1 = (d < 63) ? d : 63;
    for (int ii=i0; ii<=i1; ++ii){
      int pos = off + (ii - i0);
      int j = d - ii;
      g_ordp[LL + pos] = make_int2(ii*Ww + j, ii*Ww + (Ww-1-j));
    }
  }
}

// ---------------- x [B,L,C] -> [B,C,L] ----------------
__global__ void k_transpose(const float* __restrict__ x){
  __shared__ float tile[32][33];
  int p0 = blockIdx.x*32, c0 = blockIdx.y*32, b = blockIdx.z;
  int tx = threadIdx.x, ty = threadIdx.y;
  #pragma unroll
  for (int r=0;r<32;r+=8)
    tile[ty+r][tx] = x[((size_t)(b*LL + p0+ty+r))*Cc + c0+tx];
  __syncthreads();
  #pragma unroll
  for (int r=0;r<32;r+=8)
    g_x2d[((size_t)(b*Cc + c0+ty+r))*LL + p0+tx] = tile[tx][ty+r];
}

// ---------------- 4 depthwise convs + silu ----------------
__global__ void k_conv(const float* __restrict__ wh, const float* __restrict__ wv,
                       const float* __restrict__ wd1, const float* __restrict__ wd2){
  __shared__ float pad[22*70];
  __shared__ float swts[224];
  int r0 = blockIdx.x*16;
  int ic = blockIdx.y;
  int b  = blockIdx.z;
  int t = threadIdx.x;
  int ti = t >> 4, j0 = (t & 15)*4;

  for (int idx=t; idx<22*70; idx+=256) pad[idx] = 0.f;
  for (int idx=t; idx<224; idx+=256){
    float val;
    if (idx < 14)        val = wh[ic*14 + idx];
    else if (idx < 28)   val = wv[ic*14 + idx-14];
    else if (idx < 126)  val = wd1[ic*98 + idx-28];
    else                 val = wd2[ic*98 + idx-126];
    swts[idx] = val;
  }
  __syncthreads();
  const float* xin = g_x2d + (size_t)(b*Cc + ic)*LL;
  for (int idx=t; idx<22*64; idx+=256){
    int li = idx >> 6, j = idx & 63;
    int gi = r0 - 3 + li;
    if (gi >= 0 && gi < Hh) pad[li*70 + 3 + j] = xin[gi*Ww + j];
  }
  __syncthreads();

  const float* swh = swts;
  const float* swv = swts + 14;
  const float* sd1 = swts + 28;
  const float* sd2 = swts + 126;

  float a[8][4];
  #pragma unroll
  for (int k=0;k<8;k++)
    #pragma unroll
    for (int j=0;j<4;j++) a[k][j] = 0.f;

  #pragma unroll
  for (int ki=0; ki<7; ++ki){
    const float* prow = pad + (ti+ki)*70 + j0;
    #pragma unroll
    for (int kj=0; kj<7; ++kj){
      float w10 = sd1[ki*7+kj], w11 = sd1[49+ki*7+kj];
      float w20 = sd2[ki*7+kj], w21 = sd2[49+ki*7+kj];
      float wh0 = swh[kj], wh1 = swh[7+kj];
      float wv0 = swv[ki], wv1 = swv[7+ki];
      #pragma unroll
      for (int jx=0; jx<4; ++jx){
        float v = prow[kj + jx];
        a[4][jx] += w10*v; a[5][jx] += w11*v;
        a[6][jx] += w20*v; a[7][jx] += w21*v;
        if (ki == 3){ a[0][jx] += wh0*v; a[1][jx] += wh1*v; }
        if (kj == 3){ a[2][jx] += wv0*v; a[3][jx] += wv1*v; }
      }
    }
  }

  int gr = r0 + ti;
  #pragma unroll
  for (int k=0;k<8;k++){
    int oc = (k>>1)*Ee + 2*ic + (k&1);
    float* dst = &g_cat[((size_t)(b*CATC + oc))*LL + gr*Ww + j0];
    *(float4*)dst = make_float4(siluf(a[k][0]), siluf(a[k][1]), siluf(a[k][2]), siluf(a[k][3]));
  }
}

// ---------------- fuse 1x1 v8 (measured best): 2o tile, oh-split, group-4 --
// grid (LL/64, Bb, 8): z = ks*2+oh. block 192: oy=t>>3 (24 x 2o), px=t&7.
__global__ void __launch_bounds__(192, 4) k_fuse(){
  int p0 = blockIdx.x*64, b = blockIdx.y;
  int ks = blockIdx.z >> 1, oh = blockIdx.z & 1;
  int cb = ks*192;
  int t = threadIdx.x;
  int oy = t >> 3, px = t & 7;
  unsigned long long a00=0ull,a01=0ull,a02=0ull,a03=0ull;
  unsigned long long a10=0ull,a11=0ull,a12=0ull,a13=0ull;

  const float* xb0 = g_cat + ((size_t)(b*CATC + cb))*LL + p0 + px*4;
  const unsigned long long* wb0 = (const unsigned long long*)g_fw2
                                  + (size_t)cb*96 + oh*48 + oy*2;

  for (int g=0; g<48; ++g){
    const float* xr0 = xb0 + (size_t)(g*4+0)*LL;
    const float* xr1 = xb0 + (size_t)(g*4+1)*LL;
    const float* xr2 = xb0 + (size_t)(g*4+2)*LL;
    const float* xr3 = xb0 + (size_t)(g*4+3)*LL;
    ulonglong2 xa0 = *(const ulonglong2*)(xr0);
    ulonglong2 xc0 = *(const ulonglong2*)(xr0 + 32);
    ulonglong2 xa1 = *(const ulonglong2*)(xr1);
    ulonglong2 xc1 = *(const ulonglong2*)(xr1 + 32);
    ulonglong2 xa2 = *(const ulonglong2*)(xr2);
    ulonglong2 xc2 = *(const ulonglong2*)(xr2 + 32);
    ulonglong2 xa3 = *(const ulonglong2*)(xr3);
    ulonglong2 xc3 = *(const ulonglong2*)(xr3 + 32);
    ulonglong2 wv0 = *(const ulonglong2*)(wb0 + (size_t)(g*4+0)*96);
    ulonglong2 wv1 = *(const ulonglong2*)(wb0 + (size_t)(g*4+1)*96);
    ulonglong2 wv2 = *(const ulonglong2*)(wb0 + (size_t)(g*4+2)*96);
    ulonglong2 wv3 = *(const ulonglong2*)(wb0 + (size_t)(g*4+3)*96);

    a00=ffma2(wv0.x,xa0.x,a00); a01=ffma2(wv0.x,xa0.y,a01);
    a02=ffma2(wv0.x,xc0.x,a02); a03=ffma2(wv0.x,xc0.y,a03);
    a10=ffma2(wv0.y,xa0.x,a10); a11=ffma2(wv0.y,xa0.y,a11);
    a12=ffma2(wv0.y,xc0.x,a12); a13=ffma2(wv0.y,xc0.y,a13);

    a00=ffma2(wv1.x,xa1.x,a00); a01=ffma2(wv1.x,xa1.y,a01);
    a02=ffma2(wv1.x,xc1.x,a02); a03=ffma2(wv1.x,xc1.y,a03);
    a10=ffma2(wv1.y,xa1.x,a10); a11=ffma2(wv1.y,xa1.y,a11);
    a12=ffma2(wv1.y,xc1.x,a12); a13=ffma2(wv1.y,xc1.y,a13);

    a00=ffma2(wv2.x,xa2.x,a00); a01=ffma2(wv2.x,xa2.y,a01);
    a02=ffma2(wv2.x,xc2.x,a02); a03=ffma2(wv2.x,xc2.y,a03);
    a10=ffma2(wv2.y,xa2.x,a10); a11=ffma2(wv2.y,xa2.y,a11);
    a12=ffma2(wv2.y,xc2.x,a12); a13=ffma2(wv2.y,xc2.y,a13);

    a00=ffma2(wv3.x,xa3.x,a00); a01=ffma2(wv3.x,xa3.y,a01);
    a02=ffma2(wv3.x,xc3.x,a02); a03=ffma2(wv3.x,xc3.y,a03);
    a10=ffma2(wv3.y,xa3.x,a10); a11=ffma2(wv3.y,xa3.y,a11);
    a12=ffma2(wv3.y,xc3.x,a12); a13=ffma2(wv3.y,xc3.y,a13);
  }
  {
    int o = oh*48 + oy*2;
    float* dst0 = &g_fpart[((size_t)((ks*Bb + b)*Cc + o))*LL + p0];
    float* dst1 = dst0 + LL;
    *(ulonglong2*)&dst0[px*4]    = make_ulonglong2(a00, a01);
    *(ulonglong2*)&dst0[32+px*4] = make_ulonglong2(a02, a03);
    *(ulonglong2*)&dst1[px*4]    = make_ulonglong2(a10, a11);
    *(ulonglong2*)&dst1[32+px*4] = make_ulonglong2(a12, a13);
  }
}

// ---------------- in_proj (sums 4 fuse partials; FFMA2; writes xpT,zp) -----
__global__ void k_inproj(){
  __shared__ __align__(16) float sx[96][16];
  int l0 = blockIdx.x*16; int b = blockIdx.y;
  int t = threadIdx.x;  // 384
  const size_t PS = (size_t)Bb*Cc*LL;
  for (int idx=t; idx<96*16; idx+=384){
    int c=idx>>4, pp=idx&15;
    size_t off = (size_t)(b*Cc+c)*LL + l0+pp;
    sx[c][pp] = (g_fpart[off] + g_fpart[off+PS]) + (g_fpart[off+2*PS] + g_fpart[off+3*PS]);
  }
  __syncthreads();
  unsigned long long acc[8];
  #pragma unroll
  for (int p=0;p<8;p++) acc[p]=0ull;
  const unsigned long long* wrow = (const unsigned long long*)g_WtIn2 + t;
  for (int c=0;c<96;++c){
    unsigned long long wd = wrow[c*384];
    const ulonglong2* r = (const ulonglong2*)sx[c];
    ulonglong2 v0=r[0], v1=r[1];
    acc[0]=ffma2(wd,v0.x,acc[0]); acc[1]=ffma2(wd,v0.y,acc[1]);
    acc[2]=ffma2(wd,v1.x,acc[2]); acc[3]=ffma2(wd,v1.y,acc[3]);
    ulonglong2 v2=r[2], v3=r[3];
    acc[4]=ffma2(wd,v2.x,acc[4]); acc[5]=ffma2(wd,v2.y,acc[5]);
    acc[6]=ffma2(wd,v3.x,acc[6]); acc[7]=ffma2(wd,v3.y,acc[7]);
  }
  float y[16];
  #pragma unroll
  for (int p=0;p<8;p++) unpack2(acc[p], y[2*p], y[2*p+1]);
  if (t < 192){
    float* dst = &g_xpT[((size_t)(b*Ee + t))*LL + l0];
    #pragma unroll
    for (int k=0;k<4;k++)
      *(float4*)&dst[4*k] = make_float4(y[4*k], y[4*k+1], y[4*k+2], y[4*k+3]);
  } else {
    int j = t-192;
    #pragma unroll
    for (int p=0;p<16;++p)
      g_zp[((size_t)b*LL + l0+p)*Ee + j] = y[p];
  }
}

// ---------------- x_proj + dt (reads xpT, writes delta + BC pairs) --------
__global__ void k_xproj(const float* __restrict__ xpw, const float* __restrict__ dtw,
                        const float* __restrict__ dtb){
  __shared__ float sw[192*39];   // sw[c*39+k]
  __shared__ float xs[16*193];   // xs[l*193+c]
  __shared__ float xd[16*40];    // xd[l*40+k]
  int b = blockIdx.y; int l0 = blockIdx.x*16;
  int t = threadIdx.x;   // 256
  for (int idx=t; idx<38*192; idx+=256){
    int k = idx/192, c = idx%192;
    sw[c*39 + k] = xpw[idx];
  }
  for (int idx=t; idx<16*192; idx+=256){
    int c = idx>>4, l = idx&15;
    xs[l*193 + c] = g_xpT[((size_t)(b*Ee + c))*LL + l0+l];
  }
  __syncthreads();
  for (int idx=t; idx<16*38; idx+=256){
    int l = idx/38, k = idx%38;
    float s = 0.f;
    const float* xr = xs + l*193;
    for (int c=0;c<192;c++) s += sw[c*39+k]*xr[c];
    xd[l*40+k] = s;
  }
  __syncthreads();
  for (int idx=t; idx<16*192; idx+=256){
    int l = idx/192, e = idx%192;
    float s = 0.f;
    #pragma unroll
    for (int r=0;r<6;r++) s += dtw[e*6+r]*xd[l*40+r];
    float xx = s + 2.f*dtb[e];
    float delta = (xx > 20.f) ? xx : log1pf(__expf(xx));
    g_delta[((size_t)(b*Ee + e))*LL + l0+l] = delta;
  }
  for (int idx=t; idx<16*16; idx+=256){
    int l = idx/16, q = idx%16;
    g_BC[((size_t)(b*LL + l0+l))*Nn + q] = make_float2(xd[l*40+6+q], xd[l*40+22+q]);
  }
}

// ---------------- 4-direction selective scan ----------------
__global__ void k_scan(const float* __restrict__ A_log, const float* __restrict__ dirB,
                       const float* __restrict__ Dv){
  int e = blockIdx.x, b = blockIdx.y;
  int t = threadIdx.x, w = t>>5, lane = t&31;
  int n = lane & 15, half = lane >> 4;
  int dX = half*2, dY = dX+1;
  __shared__ float smP[16][16];
  __shared__ float smS[16][64];
  float Ane = -__expf(A_log[e*Nn + n]);
  float dbx = dirB[dX*Nn + n];
  float dby = dirB[dY*Nn + n];
  float Dval = Dv[e];
  const int bL = b*LL;
  int l0 = w*256;
  const float* dp  = g_delta + ((size_t)(b*Ee + e))*LL + l0;
  const float2* pBC = g_BC + ((size_t)(bL+l0))*Nn + n;
  const int2*  po  = g_ordp + half*LL + l0;
  const float* xpb = g_xpT + ((size_t)(b*Ee + e))*LL;

  if (w < 15){   // warp 15's chunk product feeds nobody
    float P = 1.f, sx = 0.f, sy = 0.f;
    #pragma unroll 4
    for (int k=0;k<256;++k){
      float delta = dp[k];
      float Bv = pBC[(size_t)k*Nn].x;
      int2 oo = po[k];
      float ux = xpb[oo.x];
      float uy = xpb[oo.y];
      float dA = __expf(delta*Ane);
      float dB = delta*Bv;
      sx = dA*sx + (dB + delta*dbx)*ux;
      sy = dA*sy + (dB + delta*dby)*uy;
      P *= dA;
    }
    if (half == 0) smP[w][n] = P;
    smS[w][dX*16+n] = sx;
    smS[w][dY*16+n] = sy;
  }
  __syncthreads();
  float hx = 0.f, hy = 0.f;
  for (int j=0;j<w;++j){
    float Pj = smP[j][n];
    hx = Pj*hx + smS[j][dX*16+n];
    hy = Pj*hy + smS[j][dY*16+n];
  }

  bool isY = (lane & 8) != 0;
  int dSel = dX + (isY ? 1 : 0);
  bool writer = ((lane & 7) == 0);
  #pragma unroll 4
  for (int k=0;k<256;++k){
    float delta = dp[k];
    float2 bc = pBC[(size_t)k*Nn];
    int2 oo = po[k];
    float ux = xpb[oo.x];
    float uy = xpb[oo.y];
    float dA = __expf(delta*Ane);
    float dB = delta*bc.x;
    hx = dA*hx + (dB + delta*dbx)*ux;
    hy = dA*hy + (dB + delta*dby)*uy;
    float px = hx*bc.y, py = hy*bc.y;
    px += __shfl_xor_sync(0xffffffffu, px, 8);
    py += __shfl_xor_sync(0xffffffffu, py, 8);
    float z = isY ? py : px;
    z += __shfl_xor_sync(0xffffffffu, z, 4);
    z += __shfl_xor_sync(0xffffffffu, z, 2);
    z += __shfl_xor_sync(0xffffffffu, z, 1);
    if (writer){
      int o = isY ? oo.y : oo.x;
      float u = isY ? uy : ux;
      g_yd[((size_t)(bL + o)*Ee + e)*4 + dSel] = z + Dval*u;
    }
  }
}

// ---------------- local clustering (sums 4 fuse partials) ----------------
__global__ void k_cluster(const float* __restrict__ fw, const float* __restrict__ fb,
                          const float* __restrict__ vw, const float* __restrict__ vb,
                          const float* __restrict__ pw, const float* __restrict__ pb,
                          const float* __restrict__ salpha, const float* __restrict__ sbeta){
  __shared__ float xw[96][64];
  __shared__ float fsh[6][64], vsh[6][64];
  __shared__ float cen[6][25], vc[6][25];
  __shared__ float cnorm[25], fnorm[64];
  __shared__ float ssim[25][64];
  __shared__ int   kidx[64];
  __shared__ float sval[64];
  __shared__ float rowsum[25];
  __shared__ float agg[25][6];
  __shared__ float outw[6][64];

  int wi = blockIdx.x;
  int b = wi >> 6, Wg = (wi >> 3) & 7, Hg = wi & 7;
  int t = threadIdx.x;   // 128
  const size_t PS = (size_t)Bb*Cc*LL;

  for (int idx=t; idx<96*64; idx+=128){
    int c=idx>>6, pp=idx&63;
    int i = Wg*8 + (pp>>3), j = Hg*8 + (pp&7);
    size_t off = (size_t)(b*Cc+c)*LL + i*Ww + j;
    xw[c][pp] = (g_fpart[off] + g_fpart[off+PS]) + (g_fpart[off+2*PS] + g_fpart[off+3*PS]);
  }
  __syncthreads();
  for (int idx=t; idx<2*6*64; idx+=128){
    int which = idx/384; int r = idx%384;
    int o = r>>6, pp = r&63;
    if (!which){
      float a = fb[o];
      for (int c=0;c<48;c++) a += fw[o*48+c]*xw[c][pp];
      fsh[o][pp] = a;
    } else {
      float a = vb[o];
      for (int c=0;c<48;c++) a += vw[o*48+c]*xw[48+c][pp];
      vsh[o][pp] = a;
    }
  }
  __syncthreads();
  for (int idx=t; idx<2*6*25; idx+=128){
    int which = idx/150; int r = idx%150;
    int o = r/25, k = r%25;
    int ii = k/5, jj = k%5;
    int si=(ii*8)/5, ei=((ii+1)*8+4)/5, sj=(jj*8)/5, ej=((jj+1)*8+4)/5;
    float s = 0.f;
    for (int iw=si; iw<ei; iw++)
      for (int ih=sj; ih<ej; ih++)
        s += (which ? vsh[o][iw*8+ih] : fsh[o][iw*8+ih]);
    s /= (float)((ei-si)*(ej-sj));
    if (which) vc[o][k]=s; else cen[o][k]=s;
  }
  __syncthreads();
  if (t < 25){
    float s=0.f;
    for (int o=0;o<6;o++){ float v=cen[o][t]; s+=v*v; }
    cnorm[t] = fmaxf(sqrtf(s), 1e-12f);
  } else if (t >= 64 && t < 128){
    int pp = t-64;
    float s=0.f;
    for (int o=0;o<6;o++){ float v=fsh[o][pp]; s+=v*v; }
    fnorm[pp] = fmaxf(sqrtf(s), 1e-12f);
  }
  __syncthreads();
  float alpha = salpha[0], beta = sbeta[0];
  for (int idx=t; idx<25*64; idx+=128){
    int k = idx/64, pp = idx%64;
    float dp = 0.f;
    for (int o=0;o<6;o++) dp += cen[o][k]*fsh[o][pp];
    float xarg = beta + alpha*dp/(cnorm[k]*fnorm[pp]);
    ssim[k][pp] = 1.f/(1.f + expf(-xarg));
  }
  __syncthreads();
  if (t < 64){
    float best = -1e30f; int bk = 0;
    for (int k=0;k<25;k++){ float s = ssim[k][t]; if (s > best){ best = s; bk = k; } }
    kidx[t] = bk; sval[t] = best;
  }
  __syncthreads();
  if (t < 25){
    float rs = 0.f;
    for (int p=0;p<64;p++) if (kidx[p]==t) rs += sval[p];
    rowsum[t] = rs;
  }
  __syncthreads();
  for (int idx=t; idx<25*6; idx+=128){
    int k = idx/6, c = idx%6;
    float s = 0.f;
    for (int p=0;p<64;p++) if (kidx[p]==k) s += sval[p]*vsh[c][p];
    agg[k][c] = (s + vc[c][k]) / (rowsum[k] + 1.f);
  }
  __syncthreads();
  for (int idx=t; idx<6*64; idx+=128){
    int c = idx/64, p = idx%64;
    outw[c][p] = agg[kidx[p]][c]*sval[p];
  }
  __syncthreads();
  for (int idx=t; idx<96*64; idx+=128){
    int o = idx>>6, p = idx&63;
    float a = pb[o];
    #pragma unroll
    for (int c=0;c<6;c++) a += pw[o*6+c]*outw[c][p];
    int i = Wg*8+(p>>3), j = Hg*8+(p&7);
    g_clC[(size_t)(b*Cc+o)*LL + i*Ww+j] = a;
  }
}

// ---------------- cluster_proj (FFMA2, dup weights) ----------------
__global__ void k_clproj(const float* __restrict__ cpb){
  __shared__ __align__(16) float sx[96][16];
  int l0 = blockIdx.x*16; int b = blockIdx.y;
  int t = threadIdx.x;  // 192
  for (int idx=t; idx<96*16; idx+=192){
    int c=idx>>4, pp=idx&15;
    sx[c][pp] = g_clC[(size_t)(b*Cc+c)*LL + l0+pp];
  }
  __syncthreads();
  float bi = cpb[t];
  unsigned long long acc[8];
  unsigned long long bp = pack2(bi, bi);
  #pragma unroll
  for (int p=0;p<8;p++) acc[p]=bp;
  const unsigned long long* wrow = (const unsigned long long*)g_WtCl2 + t;
  for (int c=0;c<96;++c){
    unsigned long long wd = wrow[c*192];
    const ulonglong2* r = (const ulonglong2*)sx[c];
    ulonglong2 v0=r[0], v1=r[1];
    acc[0]=ffma2(wd,v0.x,acc[0]); acc[1]=ffma2(wd,v0.y,acc[1]);
    acc[2]=ffma2(wd,v1.x,acc[2]); acc[3]=ffma2(wd,v1.y,acc[3]);
    ulonglong2 v2=r[2], v3=r[3];
    acc[4]=ffma2(wd,v2.x,acc[4]); acc[5]=ffma2(wd,v2.y,acc[5]);
    acc[6]=ffma2(wd,v3.x,acc[6]); acc[7]=ffma2(wd,v3.y,acc[7]);
  }
  float y[16];
  #pragma unroll
  for (int p=0;p<8;p++) unpack2(acc[p], y[2*p], y[2*p+1]);
  #pragma unroll
  for (int p=0;p<16;++p)
    g_cl[((size_t)b*LL + l0+p)*Ee + t] = y[p];
}

// ---------------- LN mix + out_proj ----------------
__global__ void k_mix(const float* __restrict__ lnw, const float* __restrict__ lnb,
                      const float* __restrict__ bch, float* __restrict__ out){
  int b = blockIdx.y; int l0 = blockIdx.x*8;
  int t = threadIdx.x;  // 256
  int w = t>>5, lane = t&31;
  __shared__ __align__(16) float sy[192][12];
  __shared__ float sw0[192], sw1[192], sw2[192], slw[192], slb[192];
  if (t < 192){
    float b0 = bch[t], b1 = bch[192+t], b2 = bch[384+t];
    float mx = fmaxf(b0, fmaxf(b1,b2));
    float e0=__expf(b0-mx), e1=__expf(b1-mx), e2=__expf(b2-mx);
    float inv = 1.f/(e0+e1+e2);
    sw0[t]=e0*inv; sw1[t]=e1*inv; sw2[t]=e2*inv;
    slw[t]=lnw[t]; slb[t]=lnb[t];
  }
  __syncthreads();
  int l = l0 + w;
  size_t base = ((size_t)(b*LL + l))*Ee + lane;
  float ys[6], zv[6], cv[6];
  #pragma unroll
  for (int i=0;i<6;i++){
    float4 yv = *(const float4*)&g_yd[(base + 32*i)*4];
    ys[i] = (yv.x + yv.y) + (yv.z + yv.w);
    zv[i] = g_zp[base + 32*i];
    cv[i] = g_cl[base + 32*i];
  }
  float s1=0,q1=0,s2=0,q2=0,s3=0,q3=0;
  #pragma unroll
  for (int i=0;i<6;i++){
    s1+=ys[i]; q1+=ys[i]*ys[i];
    s2+=zv[i]; q2+=zv[i]*zv[i];
    s3+=cv[i]; q3+=cv[i]*cv[i];
  }
  #pragma unroll
  for (int m=16;m;m>>=1){
    s1 += __shfl_xor_sync(0xffffffffu, s1, m);
    q1 += __shfl_xor_sync(0xffffffffu, q1, m);
    s2 += __shfl_xor_sync(0xffffffffu, s2, m);
    q2 += __shfl_xor_sync(0xffffffffu, q2, m);
    s3 += __shfl_xor_sync(0xffffffffu, s3, m);
    q3 += __shfl_xor_sync(0xffffffffu, q3, m);
  }
  const float iE = 1.f/192.f;
  float m1=s1*iE, v1=q1*iE-m1*m1;
  float m2=s2*iE, v2=q2*iE-m2*m2;
  float m3=s3*iE, v3=q3*iE-m3*m3;
  float r1=rsqrtf(v1+1e-5f), r2=rsqrtf(v2+1e-5f), r3=rsqrtf(v3+1e-5f);
  #pragma unroll
  for (int i=0;i<6;i++){
    int e = lane + 32*i;
    float lwv = slw[e], lbv = slb[e];
    float ln1=(ys[i]-m1)*r1*lwv+lbv;
    float ln2=(zv[i]-m2)*r2*lwv+lbv;
    float ln3=(cv[i]-m3)*r3*lwv+lbv;
    sy[e][w] = sw0[e]*ln1 + sw1[e]*ln2 + sw2[e]*ln3;
  }
  __syncthreads();
  if (t < 192){
    int o = t%96, hf = t/96;
    const unsigned long long* w2 = (const unsigned long long*)g_WtOut2 + o;
    unsigned long long a01=0ull, a23=0ull;
    for (int e=0;e<192;e++){
      unsigned long long wp = w2[e*96];
      float4 v = *(const float4*)&sy[e][hf*4];
      a01 = ffma2(wp, pack2(v.x, v.y), a01);
      a23 = ffma2(wp, pack2(v.z, v.w), a23);
    }
    float o0,o1,o2,o3;
    unpack2(a01, o0, o1);
    unpack2(a23, o2, o3);
    out[((size_t)(b*LL + l0+hf*4+0))*Cc + o] = o0;
    out[((size_t)(b*LL + l0+hf*4+1))*Cc + o] = o1;
    out[((size_t)(b*LL + l0+hf*4+2))*Cc + o] = o2;
    out[((size_t)(b*LL + l0+hf*4+3))*Cc + o] = o3;
  }
}

extern "C" void kernel_launch(void* const* d_in, const int* in_sizes, int n_in,
                              void* d_out, int out_size){
  const float* x    = (const float*)d_in[0];
  const float* wh   = (const float*)d_in[3];
  const float* wv   = (const float*)d_in[4];
  const float* wd1  = (const float*)d_in[5];
  const float* wd2  = (const float*)d_in[6];
  const float* fw   = (const float*)d_in[7];
  const float* inw  = (const float*)d_in[8];
  const float* xpw  = (const float*)d_in[9];
  const float* dtw  = (const float*)d_in[10];
  const float* dtb  = (const float*)d_in[11];
  const float* alog = (const float*)d_in[12];
  const float* Dv   = (const float*)d_in[13];
  const float* dirB = (const float*)d_in[14];
  const float* opw  = (const float*)d_in[15];
  const float* sal  = (const float*)d_in[16];
  const float* sbe  = (const float*)d_in[17];
  const float* f_w  = (const float*)d_in[18];
  const float* f_b  = (const float*)d_in[19];
  const float* v_w  = (const float*)d_in[20];
  const float* v_b  = (const float*)d_in[21];
  const float* p_w  = (const float*)d_in[22];
  const float* p_b  = (const float*)d_in[23];
  const float* cpb  = (const float*)d_in[25];
  const float* bch  = (const float*)d_in[26];
  const float* lnw  = (const float*)d_in[27];
  const float* lnb  = (const float*)d_in[28];
  float* out = (float*)d_out;

  k_prep<<<592, 256>>>(inw, (const float*)d_in[24], opw, fw);
  k_transpose<<<dim3(LL/32, Cc/32, Bb), dim3(32,8)>>>(x);
  k_conv<<<dim3(4, Cc, Bb), 256>>>(wh, wv, wd1, wd2);
  k_fuse<<<dim3(LL/64, Bb, 8), 192>>>();
  k_inproj<<<dim3(LL/16, Bb), 384>>>();
  k_xproj<<<dim3(LL/16, Bb), 256>>>(xpw, dtw, dtb);
  k_scan<<<dim3(Ee, Bb), 512>>>(alog, dirB, Dv);
  k_cluster<<<Bb*64, 128>>>(f_w, f_b, v_w, v_b, p_w, p_b, sal, sbe);
  k_clproj<<<dim3(LL/16, Bb), 192>>>(cpb);
  k_mix<<<dim3(LL/8, Bb), 256>>>(lnw, lnb, bch, out);
}

// round 16
// speedup vs baseline: 1.0159x; 1.0159x over previous
#include <cuda_runtime.h>
#include <math.h>

#define Bb 2
#define Hh 64
#define Ww 64
#define LL 4096
#define Cc 96
#define Ee 192
#define Nn 16
#define CATC 768

static __device__ float g_x2d  [Bb*Cc*LL];
static __device__ float g_cat  [Bb*CATC*LL];
static __device__ __align__(16) float g_fpart[4*Bb*Cc*LL];
static __device__ float g_xpT  [Bb*Ee*LL];
static __device__ float g_zp   [Bb*LL*Ee];
static __device__ float g_delta[Bb*Ee*LL];        // [B,E,L]
static __device__ __align__(8) float2 g_BC[Bb*LL*Nn];   // (B,C) pairs
static __device__ __align__(8) int2   g_ordp[2*LL];     // (ord[2p], ord[2p+1])
static __device__ __align__(16) float g_yd[Bb*LL*Ee*4];   // [B,L,E,4dirs]
static __device__ float g_clC  [Bb*Cc*LL];
static __device__ float g_cl   [Bb*LL*Ee];
static __device__ __align__(16) float2 g_WtIn2 [Cc*2*Ee]; // dup (w,w)
static __device__ __align__(16) float2 g_WtCl2 [Cc*Ee];
static __device__ __align__(8)  float2 g_WtOut2[Ee*Cc];
static __device__ __align__(16) float2 g_fw2   [CATC*Cc]; // fuse weights dup: [c][o]

__device__ __forceinline__ float siluf(float v){ return v / (1.f + __expf(-v)); }

__device__ __forceinline__ unsigned long long pack2(float x, float y){
  unsigned long long d;
  asm("mov.b64 %0, {%1, %2};" : "=l"(d) : "f"(x), "f"(y));
  return d;
}
__device__ __forceinline__ unsigned long long ffma2(unsigned long long a, unsigned long long b, unsigned long long c){
  unsigned long long d;
  asm("fma.rn.f32x2 %0, %1, %2, %3;" : "=l"(d) : "l"(a), "l"(b), "l"(c));
  return d;
}
__device__ __forceinline__ void unpack2(unsigned long long d, float& x, float& y){
  asm("mov.b64 {%0, %1}, %2;" : "=f"(x), "=f"(y) : "l"(d));
}

// ---------------- prep: orders + duplicated weight transposes --------------
__global__ void k_prep(const float* __restrict__ inw, const float* __restrict__ clw,
                       const float* __restrict__ opw, const float* __restrict__ fwm){
  int idx = blockIdx.x*256 + threadIdx.x;
  if (idx < 36864){
    int j = idx/96, c = idx%96;
    float w = inw[idx];
    g_WtIn2[c*384 + j] = make_float2(w, w);
  } else if (idx < 36864+18432){
    int r = idx - 36864;
    int e = r/96, c = r%96;
    float w = clw[r];
    g_WtCl2[c*192 + e] = make_float2(w, w);
  } else if (idx < 73728){
    int r = idx - 36864 - 18432;
    int o = r/192, e = r%192;
    float w = opw[r];
    g_WtOut2[e*96 + o] = make_float2(w, w);
  } else if (idx < 73728 + 73728){
    int r = idx - 73728;
    int o = r/768, c = r%768;
    float w = fwm[r];
    g_fw2[c*96 + o] = make_float2(w, w);
  }
  int l = idx - 147456;
  if (l >= 0 && l < LL){
    int r = l >> 6, k = l & 63;
    int i = Hh-1-r;
    int j = (r & 1) ? (Ww-1-k) : k;
    int o1 = i*Ww + j;
    int c = l >> 6, tt = l & 63;
    int i2 = (c & 1) ? (Hh-1-tt) : tt;
    g_ordp[l] = make_int2(o1, i2*Ww + c);
  }
  if (l >= 0 && l < Hh+Ww-1){
    int d = l;
    int off = (d < 64) ? d*(d+1)/2 : 2080 + (d-64)*(191-d)/2;
    int i0 = (d > 63) ? d-63 : 0;
    int i1 = (d < 63) ? d : 63;
    for (int ii=i0; ii<=i1; ++ii){
      int pos = off + (ii - i0);
      int j = d - ii;
      g_ordp[LL + pos] = make_int2(ii*Ww + j, ii*Ww + (Ww-1-j));
    }
  }
}

// ---------------- x [B,L,C] -> [B,C,L] ----------------
__global__ void k_transpose(const float* __restrict__ x){
  __shared__ float tile[32][33];
  int p0 = blockIdx.x*32, c0 = blockIdx.y*32, b = blockIdx.z;
  int tx = threadIdx.x, ty = threadIdx.y;
  #pragma unroll
  for (int r=0;r<32;r+=8)
    tile[ty+r][tx] = x[((size_t)(b*LL + p0+ty+r))*Cc + c0+tx];
  __syncthreads();
  #pragma unroll
  for (int r=0;r<32;r+=8)
    g_x2d[((size_t)(b*Cc + c0+ty+r))*LL + p0+tx] = tile[tx][ty+r];
}

// ---------------- 4 depthwise convs + silu ----------------
__global__ void k_conv(const float* __restrict__ wh, const float* __restrict__ wv,
                       const float* __restrict__ wd1, const float* __restrict__ wd2){
  __shared__ float pad[22*70];
  __shared__ float swts[224];
  int r0 = blockIdx.x*16;
  int ic = blockIdx.y;
  int b  = blockIdx.z;
  int t = threadIdx.x;
  int ti = t >> 4, j0 = (t & 15)*4;

  for (int idx=t; idx<22*70; idx+=256) pad[idx] = 0.f;
  for (int idx=t; idx<224; idx+=256){
    float val;
    if (idx < 14)        val = wh[ic*14 + idx];
    else if (idx < 28)   val = wv[ic*14 + idx-14];
    else if (idx < 126)  val = wd1[ic*98 + idx-28];
    else                 val = wd2[ic*98 + idx-126];
    swts[idx] = val;
  }
  __syncthreads();
  const float* xin = g_x2d + (size_t)(b*Cc + ic)*LL;
  for (int idx=t; idx<22*64; idx+=256){
    int li = idx >> 6, j = idx & 63;
    int gi = r0 - 3 + li;
    if (gi >= 0 && gi < Hh) pad[li*70 + 3 + j] = xin[gi*Ww + j];
  }
  __syncthreads();

  const float* swh = swts;
  const float* swv = swts + 14;
  const float* sd1 = swts + 28;
  const float* sd2 = swts + 126;

  float a[8][4];
  #pragma unroll
  for (int k=0;k<8;k++)
    #pragma unroll
    for (int j=0;j<4;j++) a[k][j] = 0.f;

  #pragma unroll
  for (int ki=0; ki<7; ++ki){
    const float* prow = pad + (ti+ki)*70 + j0;
    #pragma unroll
    for (int kj=0; kj<7; ++kj){
      float w10 = sd1[ki*7+kj], w11 = sd1[49+ki*7+kj];
      float w20 = sd2[ki*7+kj], w21 = sd2[49+ki*7+kj];
      float wh0 = swh[kj], wh1 = swh[7+kj];
      float wv0 = swv[ki], wv1 = swv[7+ki];
      #pragma unroll
      for (int jx=0; jx<4; ++jx){
        float v = prow[kj + jx];
        a[4][jx] += w10*v; a[5][jx] += w11*v;
        a[6][jx] += w20*v; a[7][jx] += w21*v;
        if (ki == 3){ a[0][jx] += wh0*v; a[1][jx] += wh1*v; }
        if (kj == 3){ a[2][jx] += wv0*v; a[3][jx] += wv1*v; }
      }
    }
  }

  int gr = r0 + ti;
  #pragma unroll
  for (int k=0;k<8;k++){
    int oc = (k>>1)*Ee + 2*ic + (k&1);
    float* dst = &g_cat[((size_t)(b*CATC + oc))*LL + gr*Ww + j0];
    *(float4*)dst = make_float4(siluf(a[k][0]), siluf(a[k][1]), siluf(a[k][2]), siluf(a[k][3]));
  }
}

// ---------------- fuse 1x1 v8 (measured best): 2o tile, oh-split, group-4 --
__global__ void __launch_bounds__(192, 4) k_fuse(){
  int p0 = blockIdx.x*64, b = blockIdx.y;
  int ks = blockIdx.z >> 1, oh = blockIdx.z & 1;
  int cb = ks*192;
  int t = threadIdx.x;
  int oy = t >> 3, px = t & 7;
  unsigned long long a00=0ull,a01=0ull,a02=0ull,a03=0ull;
  unsigned long long a10=0ull,a11=0ull,a12=0ull,a13=0ull;

  const float* xb0 = g_cat + ((size_t)(b*CATC + cb))*LL + p0 + px*4;
  const unsigned long long* wb0 = (const unsigned long long*)g_fw2
                                  + (size_t)cb*96 + oh*48 + oy*2;

  for (int g=0; g<48; ++g){
    const float* xr0 = xb0 + (size_t)(g*4+0)*LL;
    const float* xr1 = xb0 + (size_t)(g*4+1)*LL;
    const float* xr2 = xb0 + (size_t)(g*4+2)*LL;
    const float* xr3 = xb0 + (size_t)(g*4+3)*LL;
    ulonglong2 xa0 = *(const ulonglong2*)(xr0);
    ulonglong2 xc0 = *(const ulonglong2*)(xr0 + 32);
    ulonglong2 xa1 = *(const ulonglong2*)(xr1);
    ulonglong2 xc1 = *(const ulonglong2*)(xr1 + 32);
    ulonglong2 xa2 = *(const ulonglong2*)(xr2);
    ulonglong2 xc2 = *(const ulonglong2*)(xr2 + 32);
    ulonglong2 xa3 = *(const ulonglong2*)(xr3);
    ulonglong2 xc3 = *(const ulonglong2*)(xr3 + 32);
    ulonglong2 wv0 = *(const ulonglong2*)(wb0 + (size_t)(g*4+0)*96);
    ulonglong2 wv1 = *(const ulonglong2*)(wb0 + (size_t)(g*4+1)*96);
    ulonglong2 wv2 = *(const ulonglong2*)(wb0 + (size_t)(g*4+2)*96);
    ulonglong2 wv3 = *(const ulonglong2*)(wb0 + (size_t)(g*4+3)*96);

    a00=ffma2(wv0.x,xa0.x,a00); a01=ffma2(wv0.x,xa0.y,a01);
    a02=ffma2(wv0.x,xc0.x,a02); a03=ffma2(wv0.x,xc0.y,a03);
    a10=ffma2(wv0.y,xa0.x,a10); a11=ffma2(wv0.y,xa0.y,a11);
    a12=ffma2(wv0.y,xc0.x,a12); a13=ffma2(wv0.y,xc0.y,a13);

    a00=ffma2(wv1.x,xa1.x,a00); a01=ffma2(wv1.x,xa1.y,a01);
    a02=ffma2(wv1.x,xc1.x,a02); a03=ffma2(wv1.x,xc1.y,a03);
    a10=ffma2(wv1.y,xa1.x,a10); a11=ffma2(wv1.y,xa1.y,a11);
    a12=ffma2(wv1.y,xc1.x,a12); a13=ffma2(wv1.y,xc1.y,a13);

    a00=ffma2(wv2.x,xa2.x,a00); a01=ffma2(wv2.x,xa2.y,a01);
    a02=ffma2(wv2.x,xc2.x,a02); a03=ffma2(wv2.x,xc2.y,a03);
    a10=ffma2(wv2.y,xa2.x,a10); a11=ffma2(wv2.y,xa2.y,a11);
    a12=ffma2(wv2.y,xc2.x,a12); a13=ffma2(wv2.y,xc2.y,a13);

    a00=ffma2(wv3.x,xa3.x,a00); a01=ffma2(wv3.x,xa3.y,a01);
    a02=ffma2(wv3.x,xc3.x,a02); a03=ffma2(wv3.x,xc3.y,a03);
    a10=ffma2(wv3.y,xa3.x,a10); a11=ffma2(wv3.y,xa3.y,a11);
    a12=ffma2(wv3.y,xc3.x,a12); a13=ffma2(wv3.y,xc3.y,a13);
  }
  {
    int o = oh*48 + oy*2;
    float* dst0 = &g_fpart[((size_t)((ks*Bb + b)*Cc + o))*LL + p0];
    float* dst1 = dst0 + LL;
    *(ulonglong2*)&dst0[px*4]    = make_ulonglong2(a00, a01);
    *(ulonglong2*)&dst0[32+px*4] = make_ulonglong2(a02, a03);
    *(ulonglong2*)&dst1[px*4]    = make_ulonglong2(a10, a11);
    *(ulonglong2*)&dst1[32+px*4] = make_ulonglong2(a12, a13);
  }
}

// ---------------- in_proj + x_proj + dt (merged) ----------------
// block (l0=bx*16, b), 384 threads. Phase A: in_proj GEMM (sums 4 fuse
// partials). xp kept in smem; Phase B: x_proj dots, dt, delta, BC.
__global__ void k_inxp(const float* __restrict__ xpw, const float* __restrict__ dtw,
                       const float* __restrict__ dtb){
  __shared__ __align__(16) float sbuf[96*16];   // sx in phase A, xd in phase B
  __shared__ float xs[16*193];                  // xp for 16 l (row-major l)
  __shared__ float sw[192*39];                  // xpw transposed [c][k]
  float (*sx)[16] = (float(*)[16])sbuf;
  float* xd = sbuf;                             // [l*40+k], 640 floats

  int l0 = blockIdx.x*16; int b = blockIdx.y;
  int t = threadIdx.x;  // 384
  const size_t PS = (size_t)Bb*Cc*LL;
  for (int idx=t; idx<96*16; idx+=384){
    int c=idx>>4, pp=idx&15;
    size_t off = (size_t)(b*Cc+c)*LL + l0+pp;
    sx[c][pp] = (g_fpart[off] + g_fpart[off+PS]) + (g_fpart[off+2*PS] + g_fpart[off+3*PS]);
  }
  for (int idx=t; idx<38*192; idx+=384){
    int k = idx/192, c = idx%192;
    sw[c*39 + k] = xpw[idx];
  }
  __syncthreads();
  unsigned long long acc[8];
  #pragma unroll
  for (int p=0;p<8;p++) acc[p]=0ull;
  const unsigned long long* wrow = (const unsigned long long*)g_WtIn2 + t;
  for (int c=0;c<96;++c){
    unsigned long long wd = wrow[c*384];
    const ulonglong2* r = (const ulonglong2*)sx[c];
    ulonglong2 v0=r[0], v1=r[1];
    acc[0]=ffma2(wd,v0.x,acc[0]); acc[1]=ffma2(wd,v0.y,acc[1]);
    acc[2]=ffma2(wd,v1.x,acc[2]); acc[3]=ffma2(wd,v1.y,acc[3]);
    ulonglong2 v2=r[2], v3=r[3];
    acc[4]=ffma2(wd,v2.x,acc[4]); acc[5]=ffma2(wd,v2.y,acc[5]);
    acc[6]=ffma2(wd,v3.x,acc[6]); acc[7]=ffma2(wd,v3.y,acc[7]);
  }
  float y[16];
  #pragma unroll
  for (int p=0;p<8;p++) unpack2(acc[p], y[2*p], y[2*p+1]);
  __syncthreads();   // all sx reads done before xd (alias) writes below
  if (t < 192){
    float* dst = &g_xpT[((size_t)(b*Ee + t))*LL + l0];
    #pragma unroll
    for (int k=0;k<4;k++)
      *(float4*)&dst[4*k] = make_float4(y[4*k], y[4*k+1], y[4*k+2], y[4*k+3]);
    #pragma unroll
    for (int p=0;p<16;++p) xs[p*193 + t] = y[p];
  } else {
    int j = t-192;
    #pragma unroll
    for (int p=0;p<16;++p)
      g_zp[((size_t)b*LL + l0+p)*Ee + j] = y[p];
  }
  __syncthreads();
  // Phase B: x_proj dots
  for (int idx=t; idx<16*38; idx+=384){
    int l = idx/38, k = idx%38;
    float s = 0.f;
    const float* xr = xs + l*193;
    for (int c=0;c<192;c++) s += sw[c*39+k]*xr[c];
    xd[l*40+k] = s;
  }
  __syncthreads();
  for (int idx=t; idx<16*192; idx+=384){
    int l = idx/192, e = idx%192;
    float s = 0.f;
    #pragma unroll
    for (int r=0;r<6;r++) s += dtw[e*6+r]*xd[l*40+r];
    float xx = s + 2.f*dtb[e];
    float delta = (xx > 20.f) ? xx : log1pf(__expf(xx));
    g_delta[((size_t)(b*Ee + e))*LL + l0+l] = delta;
  }
  for (int idx=t; idx<16*16; idx+=384){
    int l = idx/16, q = idx%16;
    g_BC[((size_t)(b*LL + l0+l))*Nn + q] = make_float2(xd[l*40+6+q], xd[l*40+22+q]);
  }
}

// ---------------- 4-direction selective scan ----------------
__global__ void k_scan(const float* __restrict__ A_log, const float* __restrict__ dirB,
                       const float* __restrict__ Dv){
  int e = blockIdx.x, b = blockIdx.y;
  int t = threadIdx.x, w = t>>5, lane = t&31;
  int n = lane & 15, half = lane >> 4;
  int dX = half*2, dY = dX+1;
  __shared__ float smP[16][16];
  __shared__ float smS[16][64];
  float Ane = -__expf(A_log[e*Nn + n]);
  float dbx = dirB[dX*Nn + n];
  float dby = dirB[dY*Nn + n];
  float Dval = Dv[e];
  const int bL = b*LL;
  int l0 = w*256;
  const float* dp  = g_delta + ((size_t)(b*Ee + e))*LL + l0;
  const float2* pBC = g_BC + ((size_t)(bL+l0))*Nn + n;
  const int2*  po  = g_ordp + half*LL + l0;
  const float* xpb = g_xpT + ((size_t)(b*Ee + e))*LL;

  if (w < 15){
    float P = 1.f, sx = 0.f, sy = 0.f;
    #pragma unroll 4
    for (int k=0;k<256;++k){
      float delta = dp[k];
      float Bv = pBC[(size_t)k*Nn].x;
      int2 oo = po[k];
      float ux = xpb[oo.x];
      float uy = xpb[oo.y];
      float dA = __expf(delta*Ane);
      float dB = delta*Bv;
      sx = dA*sx + (dB + delta*dbx)*ux;
      sy = dA*sy + (dB + delta*dby)*uy;
      P *= dA;
    }
    if (half == 0) smP[w][n] = P;
    smS[w][dX*16+n] = sx;
    smS[w][dY*16+n] = sy;
  }
  __syncthreads();
  float hx = 0.f, hy = 0.f;
  for (int j=0;j<w;++j){
    float Pj = smP[j][n];
    hx = Pj*hx + smS[j][dX*16+n];
    hy = Pj*hy + smS[j][dY*16+n];
  }

  bool isY = (lane & 8) != 0;
  int dSel = dX + (isY ? 1 : 0);
  bool writer = ((lane & 7) == 0);
  #pragma unroll 4
  for (int k=0;k<256;++k){
    float delta = dp[k];
    float2 bc = pBC[(size_t)k*Nn];
    int2 oo = po[k];
    float ux = xpb[oo.x];
    float uy = xpb[oo.y];
    float dA = __expf(delta*Ane);
    float dB = delta*bc.x;
    hx = dA*hx + (dB + delta*dbx)*ux;
    hy = dA*hy + (dB + delta*dby)*uy;
    float px = hx*bc.y, py = hy*bc.y;
    px += __shfl_xor_sync(0xffffffffu, px, 8);
    py += __shfl_xor_sync(0xffffffffu, py, 8);
    float z = isY ? py : px;
    z += __shfl_xor_sync(0xffffffffu, z, 4);
    z += __shfl_xor_sync(0xffffffffu, z, 2);
    z += __shfl_xor_sync(0xffffffffu, z, 1);
    if (writer){
      int o = isY ? oo.y : oo.x;
      float u = isY ? uy : ux;
      g_yd[((size_t)(bL + o)*Ee + e)*4 + dSel] = z + Dval*u;
    }
  }
}

// ---------------- local clustering (sums 4 fuse partials) ----------------
__global__ void k_cluster(const float* __restrict__ fw, const float* __restrict__ fb,
                          const float* __restrict__ vw, const float* __restrict__ vb,
                          const float* __restrict__ pw, const float* __restrict__ pb,
                          const float* __restrict__ salpha, const float* __restrict__ sbeta){
  __shared__ float xw[96][64];
  __shared__ float fsh[6][64], vsh[6][64];
  __shared__ float cen[6][25], vc[6][25];
  __shared__ float cnorm[25], fnorm[64];
  __shared__ float ssim[25][64];
  __shared__ int   kidx[64];
  __shared__ float sval[64];
  __shared__ float rowsum[25];
  __shared__ float agg[25][6];
  __shared__ float outw[6][64];

  int wi = blockIdx.x;
  int b = wi >> 6, Wg = (wi >> 3) & 7, Hg = wi & 7;
  int t = threadIdx.x;   // 128
  const size_t PS = (size_t)Bb*Cc*LL;

  for (int idx=t; idx<96*64; idx+=128){
    int c=idx>>6, pp=idx&63;
    int i = Wg*8 + (pp>>3), j = Hg*8 + (pp&7);
    size_t off = (size_t)(b*Cc+c)*LL + i*Ww + j;
    xw[c][pp] = (g_fpart[off] + g_fpart[off+PS]) + (g_fpart[off+2*PS] + g_fpart[off+3*PS]);
  }
  __syncthreads();
  for (int idx=t; idx<2*6*64; idx+=128){
    int which = idx/384; int r = idx%384;
    int o = r>>6, pp = r&63;
    if (!which){
      float a = fb[o];
      for (int c=0;c<48;c++) a += fw[o*48+c]*xw[c][pp];
      fsh[o][pp] = a;
    } else {
      float a = vb[o];
      for (int c=0;c<48;c++) a += vw[o*48+c]*xw[48+c][pp];
      vsh[o][pp] = a;
    }
  }
  __syncthreads();
  for (int idx=t; idx<2*6*25; idx+=128){
    int which = idx/150; int r = idx%150;
    int o = r/25, k = r%25;
    int ii = k/5, jj = k%5;
    int si=(ii*8)/5, ei=((ii+1)*8+4)/5, sj=(jj*8)/5, ej=((jj+1)*8+4)/5;
    float s = 0.f;
    for (int iw=si; iw<ei; iw++)
      for (int ih=sj; ih<ej; ih++)
        s += (which ? vsh[o][iw*8+ih] : fsh[o][iw*8+ih]);
    s /= (float)((ei-si)*(ej-sj));
    if (which) vc[o][k]=s; else cen[o][k]=s;
  }
  __syncthreads();
  if (t < 25){
    float s=0.f;
    for (int o=0;o<6;o++){ float v=cen[o][t]; s+=v*v; }
    cnorm[t] = fmaxf(sqrtf(s), 1e-12f);
  } else if (t >= 64 && t < 128){
    int pp = t-64;
    float s=0.f;
    for (int o=0;o<6;o++){ float v=fsh[o][pp]; s+=v*v; }
    fnorm[pp] = fmaxf(sqrtf(s), 1e-12f);
  }
  __syncthreads();
  float alpha = salpha[0], beta = sbeta[0];
  for (int idx=t; idx<25*64; idx+=128){
    int k = idx/64, pp = idx%64;
    float dp = 0.f;
    for (int o=0;o<6;o++) dp += cen[o][k]*fsh[o][pp];
    float xarg = beta + alpha*dp/(cnorm[k]*fnorm[pp]);
    ssim[k][pp] = 1.f/(1.f + expf(-xarg));
  }
  __syncthreads();
  if (t < 64){
    float best = -1e30f; int bk = 0;
    for (int k=0;k<25;k++){ float s = ssim[k][t]; if (s > best){ best = s; bk = k; } }
    kidx[t] = bk; sval[t] = best;
  }
  __syncthreads();
  if (t < 25){
    float rs = 0.f;
    for (int p=0;p<64;p++) if (kidx[p]==t) rs += sval[p];
    rowsum[t] = rs;
  }
  __syncthreads();
  for (int idx=t; idx<25*6; idx+=128){
    int k = idx/6, c = idx%6;
    float s = 0.f;
    for (int p=0;p<64;p++) if (kidx[p]==k) s += sval[p]*vsh[c][p];
    agg[k][c] = (s + vc[c][k]) / (rowsum[k] + 1.f);
  }
  __syncthreads();
  for (int idx=t; idx<6*64; idx+=128){
    int c = idx/64, p = idx%64;
    outw[c][p] = agg[kidx[p]][c]*sval[p];
  }
  __syncthreads();
  for (int idx=t; idx<96*64; idx+=128){
    int o = idx>>6, p = idx&63;
    float a = pb[o];
    #pragma unroll
    for (int c=0;c<6;c++) a += pw[o*6+c]*outw[c][p];
    int i = Wg*8+(p>>3), j = Hg*8+(p&7);
    g_clC[(size_t)(b*Cc+o)*LL + i*Ww+j] = a;
  }
}

// ---------------- cluster_proj (FFMA2, dup weights) ----------------
__global__ void k_clproj(const float* __restrict__ cpb){
  __shared__ __align__(16) float sx[96][16];
  int l0 = blockIdx.x*16; int b = blockIdx.y;
  int t = threadIdx.x;  // 192
  for (int idx=t; idx<96*16; idx+=192){
    int c=idx>>4, pp=idx&15;
    sx[c][pp] = g_clC[(size_t)(b*Cc+c)*LL + l0+pp];
  }
  __syncthreads();
  float bi = cpb[t];
  unsigned long long acc[8];
  unsigned long long bp = pack2(bi, bi);
  #pragma unroll
  for (int p=0;p<8;p++) acc[p]=bp;
  const unsigned long long* wrow = (const unsigned long long*)g_WtCl2 + t;
  for (int c=0;c<96;++c){
    unsigned long long wd = wrow[c*192];
    const ulonglong2* r = (const ulonglong2*)sx[c];
    ulonglong2 v0=r[0], v1=r[1];
    acc[0]=ffma2(wd,v0.x,acc[0]); acc[1]=ffma2(wd,v0.y,acc[1]);
    acc[2]=ffma2(wd,v1.x,acc[2]); acc[3]=ffma2(wd,v1.y,acc[3]);
    ulonglong2 v2=r[2], v3=r[3];
    acc[4]=ffma2(wd,v2.x,acc[4]); acc[5]=ffma2(wd,v2.y,acc[5]);
    acc[6]=ffma2(wd,v3.x,acc[6]); acc[7]=ffma2(wd,v3.y,acc[7]);
  }
  float y[16];
  #pragma unroll
  for (int p=0;p<8;p++) unpack2(acc[p], y[2*p], y[2*p+1]);
  #pragma unroll
  for (int p=0;p<16;++p)
    g_cl[((size_t)b*LL + l0+p)*Ee + t] = y[p];
}

// ---------------- LN mix + out_proj ----------------
__global__ void k_mix(const float* __restrict__ lnw, const float* __restrict__ lnb,
                      const float* __restrict__ bch, float* __restrict__ out){
  int b = blockIdx.y; int l0 = blockIdx.x*8;
  int t = threadIdx.x;  // 256
  int w = t>>5, lane = t&31;
  __shared__ __align__(16) float sy[192][12];
  __shared__ float sw0[192], sw1[192], sw2[192], slw[192], slb[192];
  if (t < 192){
    float b0 = bch[t], b1 = bch[192+t], b2 = bch[384+t];
    float mx = fmaxf(b0, fmaxf(b1,b2));
    float e0=__expf(b0-mx), e1=__expf(b1-mx), e2=__expf(b2-mx);
    float inv = 1.f/(e0+e1+e2);
    sw0[t]=e0*inv; sw1[t]=e1*inv; sw2[t]=e2*inv;
    slw[t]=lnw[t]; slb[t]=lnb[t];
  }
  __syncthreads();
  int l = l0 + w;
  size_t base = ((size_t)(b*LL + l))*Ee + lane;
  float ys[6], zv[6], cv[6];
  #pragma unroll
  for (int i=0;i<6;i++){
    float4 yv = *(const float4*)&g_yd[(base + 32*i)*4];
    ys[i] = (yv.x + yv.y) + (yv.z + yv.w);
    zv[i] = g_zp[base + 32*i];
    cv[i] = g_cl[base + 32*i];
  }
  float s1=0,q1=0,s2=0,q2=0,s3=0,q3=0;
  #pragma unroll
  for (int i=0;i<6;i++){
    s1+=ys[i]; q1+=ys[i]*ys[i];
    s2+=zv[i]; q2+=zv[i]*zv[i];
    s3+=cv[i]; q3+=cv[i]*cv[i];
  }
  #pragma unroll
  for (int m=16;m;m>>=1){
    s1 += __shfl_xor_sync(0xffffffffu, s1, m);
    q1 += __shfl_xor_sync(0xffffffffu, q1, m);
    s2 += __shfl_xor_sync(0xffffffffu, s2, m);
    q2 += __shfl_xor_sync(0xffffffffu, q2, m);
    s3 += __shfl_xor_sync(0xffffffffu, s3, m);
    q3 += __shfl_xor_sync(0xffffffffu, q3, m);
  }
  const float iE = 1.f/192.f;
  float m1=s1*iE, v1=q1*iE-m1*m1;
  float m2=s2*iE, v2=q2*iE-m2*m2;
  float m3=s3*iE, v3=q3*iE-m3*m3;
  float r1=rsqrtf(v1+1e-5f), r2=rsqrtf(v2+1e-5f), r3=rsqrtf(v3+1e-5f);
  #pragma unroll
  for (int i=0;i<6;i++){
    int e = lane + 32*i;
    float lwv = slw[e], lbv = slb[e];
    float ln1=(ys[i]-m1)*r1*lwv+lbv;
    float ln2=(zv[i]-m2)*r2*lwv+lbv;
    float ln3=(cv[i]-m3)*r3*lwv+lbv;
    sy[e][w] = sw0[e]*ln1 + sw1[e]*ln2 + sw2[e]*ln3;
  }
  __syncthreads();
  if (t < 192){
    int o = t%96, hf = t/96;
    const unsigned long long* w2 = (const unsigned long long*)g_WtOut2 + o;
    unsigned long long a01=0ull, a23=0ull;
    for (int e=0;e<192;e++){
      unsigned long long wp = w2[e*96];
      float4 v = *(const float4*)&sy[e][hf*4];
      a01 = ffma2(wp, pack2(v.x, v.y), a01);
      a23 = ffma2(wp, pack2(v.z, v.w), a23);
    }
    float o0,o1,o2,o3;
    unpack2(a01, o0, o1);
    unpack2(a23, o2, o3);
    out[((size_t)(b*LL + l0+hf*4+0))*Cc + o] = o0;
    out[((size_t)(b*LL + l0+hf*4+1))*Cc + o] = o1;
    out[((size_t)(b*LL + l0+hf*4+2))*Cc + o] = o2;
    out[((size_t)(b*LL + l0+hf*4+3))*Cc + o] = o3;
  }
}

extern "C" void kernel_launch(void* const* d_in, const int* in_sizes, int n_in,
                              void* d_out, int out_size){
  const float* x    = (const float*)d_in[0];
  const float* wh   = (const float*)d_in[3];
  const float* wv   = (const float*)d_in[4];
  const float* wd1  = (const float*)d_in[5];
  const float* wd2  = (const float*)d_in[6];
  const float* fw   = (const float*)d_in[7];
  const float* inw  = (const float*)d_in[8];
  const float* xpw  = (const float*)d_in[9];
  const float* dtw  = (const float*)d_in[10];
  const float* dtb  = (const float*)d_in[11];
  const float* alog = (const float*)d_in[12];
  const float* Dv   = (const float*)d_in[13];
  const float* dirB = (const float*)d_in[14];
  const float* opw  = (const float*)d_in[15];
  const float* sal  = (const float*)d_in[16];
  const float* sbe  = (const float*)d_in[17];
  const float* f_w  = (const float*)d_in[18];
  const float* f_b  = (const float*)d_in[19];
  const float* v_w  = (const float*)d_in[20];
  const float* v_b  = (const float*)d_in[21];
  const float* p_w  = (const float*)d_in[22];
  const float* p_b  = (const float*)d_in[23];
  const float* cpb  = (const float*)d_in[25];
  const float* bch  = (const float*)d_in[26];
  const float* lnw  = (const float*)d_in[27];
  const float* lnb  = (const float*)d_in[28];
  float* out = (float*)d_out;

  k_prep<<<592, 256>>>(inw, (const float*)d_in[24], opw, fw);
  k_transpose<<<dim3(LL/32, Cc/32, Bb), dim3(32,8)>>>(x);
  k_conv<<<dim3(4, Cc, Bb), 256>>>(wh, wv, wd1, wd2);
  k_fuse<<<dim3(LL/64, Bb, 8), 192>>>();
  k_inxp<<<dim3(LL/16, Bb), 384>>>(xpw, dtw, dtb);
  k_scan<<<dim3(Ee, Bb), 512>>>(alog, dirB, Dv);
  k_cluster<<<Bb*64, 128>>>(f_w, f_b, v_w, v_b, p_w, p_b, sal, sbe);
  k_clproj<<<dim3(LL/16, Bb), 192>>>(cpb);
  k_mix<<<dim3(LL/8, Bb), 256>>>(lnw, lnb, bch, out);
}

// round 17
// speedup vs baseline: 1.0773x; 1.0604x over previous
#include <cuda_runtime.h>
#include <math.h>

#define Bb 2
#define Hh 64
#define Ww 64
#define LL 4096
#define Cc 96
#define Ee 192
#define Nn 16
#define CATC 768

static __device__ float g_x2d  [Bb*Cc*LL];
static __device__ float g_cat  [Bb*CATC*LL];
static __device__ __align__(16) float g_fpart[4*Bb*Cc*LL];
static __device__ __align__(16) float g_xpT  [Bb*Ee*LL];
static __device__ float g_zp   [Bb*LL*Ee];
static __device__ __align__(16) float g_delta[Bb*Ee*LL];  // [B,E,L]
static __device__ __align__(8) float2 g_BC[Bb*LL*Nn];   // (B,C) pairs
static __device__ __align__(8) int2   g_ordp[2*LL];     // (ord[2p], ord[2p+1])
static __device__ __align__(16) float g_yd[Bb*LL*Ee*4];   // [B,L,E,4dirs]
static __device__ float g_clC  [Bb*Cc*LL];
static __device__ float g_cl   [Bb*LL*Ee];
static __device__ __align__(16) float2 g_WtIn2 [Cc*2*Ee]; // dup (w,w)
static __device__ __align__(16) float2 g_WtCl2 [Cc*Ee];
static __device__ __align__(8)  float2 g_WtOut2[Ee*Cc];
static __device__ __align__(16) float2 g_fw2   [CATC*Cc]; // fuse weights dup: [c][o]

__device__ __forceinline__ float siluf(float v){ return v / (1.f + __expf(-v)); }

__device__ __forceinline__ unsigned long long pack2(float x, float y){
  unsigned long long d;
  asm("mov.b64 %0, {%1, %2};" : "=l"(d) : "f"(x), "f"(y));
  return d;
}
__device__ __forceinline__ unsigned long long ffma2(unsigned long long a, unsigned long long b, unsigned long long c){
  unsigned long long d;
  asm("fma.rn.f32x2 %0, %1, %2, %3;" : "=l"(d) : "l"(a), "l"(b), "l"(c));
  return d;
}
__device__ __forceinline__ void unpack2(unsigned long long d, float& x, float& y){
  asm("mov.b64 {%0, %1}, %2;" : "=f"(x), "=f"(y) : "l"(d));
}

// ---------------- prep: orders + duplicated weight transposes --------------
__global__ void k_prep(const float* __restrict__ inw, const float* __restrict__ clw,
                       const float* __restrict__ opw, const float* __restrict__ fwm){
  int idx = blockIdx.x*256 + threadIdx.x;
  if (idx < 36864){
    int j = idx/96, c = idx%96;
    float w = inw[idx];
    g_WtIn2[c*384 + j] = make_float2(w, w);
  } else if (idx < 36864+18432){
    int r = idx - 36864;
    int e = r/96, c = r%96;
    float w = clw[r];
    g_WtCl2[c*192 + e] = make_float2(w, w);
  } else if (idx < 73728){
    int r = idx - 36864 - 18432;
    int o = r/192, e = r%192;
    float w = opw[r];
    g_WtOut2[e*96 + o] = make_float2(w, w);
  } else if (idx < 73728 + 73728){
    int r = idx - 73728;
    int o = r/768, c = r%768;
    float w = fwm[r];
    g_fw2[c*96 + o] = make_float2(w, w);
  }
  int l = idx - 147456;
  if (l >= 0 && l < LL){
    int r = l >> 6, k = l & 63;
    int i = Hh-1-r;
    int j = (r & 1) ? (Ww-1-k) : k;
    int o1 = i*Ww + j;
    int c = l >> 6, tt = l & 63;
    int i2 = (c & 1) ? (Hh-1-tt) : tt;
    g_ordp[l] = make_int2(o1, i2*Ww + c);
  }
  if (l >= 0 && l < Hh+Ww-1){
    int d = l;
    int off = (d < 64) ? d*(d+1)/2 : 2080 + (d-64)*(191-d)/2;
    int i0 = (d > 63) ? d-63 : 0;
    int i1 = (d < 63) ? d : 63;
    for (int ii=i0; ii<=i1; ++ii){
      int pos = off + (ii - i0);
      int j = d - ii;
      g_ordp[LL + pos] = make_int2(ii*Ww + j, ii*Ww + (Ww-1-j));
    }
  }
}

// ---------------- x [B,L,C] -> [B,C,L] ----------------
__global__ void k_transpose(const float* __restrict__ x){
  __shared__ float tile[32][33];
  int p0 = blockIdx.x*32, c0 = blockIdx.y*32, b = blockIdx.z;
  int tx = threadIdx.x, ty = threadIdx.y;
  #pragma unroll
  for (int r=0;r<32;r+=8)
    tile[ty+r][tx] = x[((size_t)(b*LL + p0+ty+r))*Cc + c0+tx];
  __syncthreads();
  #pragma unroll
  for (int r=0;r<32;r+=8)
    g_x2d[((size_t)(b*Cc + c0+ty+r))*LL + p0+tx] = tile[tx][ty+r];
}

// ---------------- 4 depthwise convs + silu ----------------
__global__ void k_conv(const float* __restrict__ wh, const float* __restrict__ wv,
                       const float* __restrict__ wd1, const float* __restrict__ wd2){
  __shared__ float pad[22*70];
  __shared__ float swts[224];
  int r0 = blockIdx.x*16;
  int ic = blockIdx.y;
  int b  = blockIdx.z;
  int t = threadIdx.x;
  int ti = t >> 4, j0 = (t & 15)*4;

  for (int idx=t; idx<22*70; idx+=256) pad[idx] = 0.f;
  for (int idx=t; idx<224; idx+=256){
    float val;
    if (idx < 14)        val = wh[ic*14 + idx];
    else if (idx < 28)   val = wv[ic*14 + idx-14];
    else if (idx < 126)  val = wd1[ic*98 + idx-28];
    else                 val = wd2[ic*98 + idx-126];
    swts[idx] = val;
  }
  __syncthreads();
  const float* xin = g_x2d + (size_t)(b*Cc + ic)*LL;
  for (int idx=t; idx<22*64; idx+=256){
    int li = idx >> 6, j = idx & 63;
    int gi = r0 - 3 + li;
    if (gi >= 0 && gi < Hh) pad[li*70 + 3 + j] = xin[gi*Ww + j];
  }
  __syncthreads();

  const float* swh = swts;
  const float* swv = swts + 14;
  const float* sd1 = swts + 28;
  const float* sd2 = swts + 126;

  float a[8][4];
  #pragma unroll
  for (int k=0;k<8;k++)
    #pragma unroll
    for (int j=0;j<4;j++) a[k][j] = 0.f;

  #pragma unroll
  for (int ki=0; ki<7; ++ki){
    const float* prow = pad + (ti+ki)*70 + j0;
    #pragma unroll
    for (int kj=0; kj<7; ++kj){
      float w10 = sd1[ki*7+kj], w11 = sd1[49+ki*7+kj];
      float w20 = sd2[ki*7+kj], w21 = sd2[49+ki*7+kj];
      float wh0 = swh[kj], wh1 = swh[7+kj];
      float wv0 = swv[ki], wv1 = swv[7+ki];
      #pragma unroll
      for (int jx=0; jx<4; ++jx){
        float v = prow[kj + jx];
        a[4][jx] += w10*v; a[5][jx] += w11*v;
        a[6][jx] += w20*v; a[7][jx] += w21*v;
        if (ki == 3){ a[0][jx] += wh0*v; a[1][jx] += wh1*v; }
        if (kj == 3){ a[2][jx] += wv0*v; a[3][jx] += wv1*v; }
      }
    }
  }

  int gr = r0 + ti;
  #pragma unroll
  for (int k=0;k<8;k++){
    int oc = (k>>1)*Ee + 2*ic + (k&1);
    float* dst = &g_cat[((size_t)(b*CATC + oc))*LL + gr*Ww + j0];
    *(float4*)dst = make_float4(siluf(a[k][0]), siluf(a[k][1]), siluf(a[k][2]), siluf(a[k][3]));
  }
}

// ---------------- fuse 1x1 v8 (measured best): 2o tile, oh-split, group-4 --
__global__ void __launch_bounds__(192, 4) k_fuse(){
  int p0 = blockIdx.x*64, b = blockIdx.y;
  int ks = blockIdx.z >> 1, oh = blockIdx.z & 1;
  int cb = ks*192;
  int t = threadIdx.x;
  int oy = t >> 3, px = t & 7;
  unsigned long long a00=0ull,a01=0ull,a02=0ull,a03=0ull;
  unsigned long long a10=0ull,a11=0ull,a12=0ull,a13=0ull;

  const float* xb0 = g_cat + ((size_t)(b*CATC + cb))*LL + p0 + px*4;
  const unsigned long long* wb0 = (const unsigned long long*)g_fw2
                                  + (size_t)cb*96 + oh*48 + oy*2;

  for (int g=0; g<48; ++g){
    const float* xr0 = xb0 + (size_t)(g*4+0)*LL;
    const float* xr1 = xb0 + (size_t)(g*4+1)*LL;
    const float* xr2 = xb0 + (size_t)(g*4+2)*LL;
    const float* xr3 = xb0 + (size_t)(g*4+3)*LL;
    ulonglong2 xa0 = *(const ulonglong2*)(xr0);
    ulonglong2 xc0 = *(const ulonglong2*)(xr0 + 32);
    ulonglong2 xa1 = *(const ulonglong2*)(xr1);
    ulonglong2 xc1 = *(const ulonglong2*)(xr1 + 32);
    ulonglong2 xa2 = *(const ulonglong2*)(xr2);
    ulonglong2 xc2 = *(const ulonglong2*)(xr2 + 32);
    ulonglong2 xa3 = *(const ulonglong2*)(xr3);
    ulonglong2 xc3 = *(const ulonglong2*)(xr3 + 32);
    ulonglong2 wv0 = *(const ulonglong2*)(wb0 + (size_t)(g*4+0)*96);
    ulonglong2 wv1 = *(const ulonglong2*)(wb0 + (size_t)(g*4+1)*96);
    ulonglong2 wv2 = *(const ulonglong2*)(wb0 + (size_t)(g*4+2)*96);
    ulonglong2 wv3 = *(const ulonglong2*)(wb0 + (size_t)(g*4+3)*96);

    a00=ffma2(wv0.x,xa0.x,a00); a01=ffma2(wv0.x,xa0.y,a01);
    a02=ffma2(wv0.x,xc0.x,a02); a03=ffma2(wv0.x,xc0.y,a03);
    a10=ffma2(wv0.y,xa0.x,a10); a11=ffma2(wv0.y,xa0.y,a11);
    a12=ffma2(wv0.y,xc0.x,a12); a13=ffma2(wv0.y,xc0.y,a13);

    a00=ffma2(wv1.x,xa1.x,a00); a01=ffma2(wv1.x,xa1.y,a01);
    a02=ffma2(wv1.x,xc1.x,a02); a03=ffma2(wv1.x,xc1.y,a03);
    a10=ffma2(wv1.y,xa1.x,a10); a11=ffma2(wv1.y,xa1.y,a11);
    a12=ffma2(wv1.y,xc1.x,a12); a13=ffma2(wv1.y,xc1.y,a13);

    a00=ffma2(wv2.x,xa2.x,a00); a01=ffma2(wv2.x,xa2.y,a01);
    a02=ffma2(wv2.x,xc2.x,a02); a03=ffma2(wv2.x,xc2.y,a03);
    a10=ffma2(wv2.y,xa2.x,a10); a11=ffma2(wv2.y,xa2.y,a11);
    a12=ffma2(wv2.y,xc2.x,a12); a13=ffma2(wv2.y,xc2.y,a13);

    a00=ffma2(wv3.x,xa3.x,a00); a01=ffma2(wv3.x,xa3.y,a01);
    a02=ffma2(wv3.x,xc3.x,a02); a03=ffma2(wv3.x,xc3.y,a03);
    a10=ffma2(wv3.y,xa3.x,a10); a11=ffma2(wv3.y,xa3.y,a11);
    a12=ffma2(wv3.y,xc3.x,a12); a13=ffma2(wv3.y,xc3.y,a13);
  }
  {
    int o = oh*48 + oy*2;
    float* dst0 = &g_fpart[((size_t)((ks*Bb + b)*Cc + o))*LL + p0];
    float* dst1 = dst0 + LL;
    *(ulonglong2*)&dst0[px*4]    = make_ulonglong2(a00, a01);
    *(ulonglong2*)&dst0[32+px*4] = make_ulonglong2(a02, a03);
    *(ulonglong2*)&dst1[px*4]    = make_ulonglong2(a10, a11);
    *(ulonglong2*)&dst1[32+px*4] = make_ulonglong2(a12, a13);
  }
}

// ---------------- in_proj + x_proj + dt (merged) ----------------
__global__ void k_inxp(const float* __restrict__ xpw, const float* __restrict__ dtw,
                       const float* __restrict__ dtb){
  __shared__ __align__(16) float sbuf[96*16];   // sx in phase A, xd in phase B
  __shared__ float xs[16*193];                  // xp for 16 l (row-major l)
  __shared__ float sw[192*39];                  // xpw transposed [c][k]
  float (*sx)[16] = (float(*)[16])sbuf;
  float* xd = sbuf;                             // [l*40+k], 640 floats

  int l0 = blockIdx.x*16; int b = blockIdx.y;
  int t = threadIdx.x;  // 384
  const size_t PS = (size_t)Bb*Cc*LL;
  for (int idx=t; idx<96*16; idx+=384){
    int c=idx>>4, pp=idx&15;
    size_t off = (size_t)(b*Cc+c)*LL + l0+pp;
    sx[c][pp] = (g_fpart[off] + g_fpart[off+PS]) + (g_fpart[off+2*PS] + g_fpart[off+3*PS]);
  }
  for (int idx=t; idx<38*192; idx+=384){
    int k = idx/192, c = idx%192;
    sw[c*39 + k] = xpw[idx];
  }
  __syncthreads();
  unsigned long long acc[8];
  #pragma unroll
  for (int p=0;p<8;p++) acc[p]=0ull;
  const unsigned long long* wrow = (const unsigned long long*)g_WtIn2 + t;
  for (int c=0;c<96;++c){
    unsigned long long wd = wrow[c*384];
    const ulonglong2* r = (const ulonglong2*)sx[c];
    ulonglong2 v0=r[0], v1=r[1];
    acc[0]=ffma2(wd,v0.x,acc[0]); acc[1]=ffma2(wd,v0.y,acc[1]);
    acc[2]=ffma2(wd,v1.x,acc[2]); acc[3]=ffma2(wd,v1.y,acc[3]);
    ulonglong2 v2=r[2], v3=r[3];
    acc[4]=ffma2(wd,v2.x,acc[4]); acc[5]=ffma2(wd,v2.y,acc[5]);
    acc[6]=ffma2(wd,v3.x,acc[6]); acc[7]=ffma2(wd,v3.y,acc[7]);
  }
  float y[16];
  #pragma unroll
  for (int p=0;p<8;p++) unpack2(acc[p], y[2*p], y[2*p+1]);
  __syncthreads();
  if (t < 192){
    float* dst = &g_xpT[((size_t)(b*Ee + t))*LL + l0];
    #pragma unroll
    for (int k=0;k<4;k++)
      *(float4*)&dst[4*k] = make_float4(y[4*k], y[4*k+1], y[4*k+2], y[4*k+3]);
    #pragma unroll
    for (int p=0;p<16;++p) xs[p*193 + t] = y[p];
  } else {
    int j = t-192;
    #pragma unroll
    for (int p=0;p<16;++p)
      g_zp[((size_t)b*LL + l0+p)*Ee + j] = y[p];
  }
  __syncthreads();
  for (int idx=t; idx<16*38; idx+=384){
    int l = idx/38, k = idx%38;
    float s = 0.f;
    const float* xr = xs + l*193;
    for (int c=0;c<192;c++) s += sw[c*39+k]*xr[c];
    xd[l*40+k] = s;
  }
  __syncthreads();
  for (int idx=t; idx<16*192; idx+=384){
    int l = idx/192, e = idx%192;
    float s = 0.f;
    #pragma unroll
    for (int r=0;r<6;r++) s += dtw[e*6+r]*xd[l*40+r];
    float xx = s + 2.f*dtb[e];
    float delta = (xx > 20.f) ? xx : log1pf(__expf(xx));
    g_delta[((size_t)(b*Ee + e))*LL + l0+l] = delta;
  }
  for (int idx=t; idx<16*16; idx+=384){
    int l = idx/16, q = idx%16;
    g_BC[((size_t)(b*LL + l0+l))*Nn + q] = make_float2(xd[l*40+6+q], xd[l*40+22+q]);
  }
}

// ---------------- 4-direction selective scan (smem-staged rows) -----------
__global__ void __launch_bounds__(512) k_scan(const float* __restrict__ A_log,
                       const float* __restrict__ dirB, const float* __restrict__ Dv){
  __shared__ __align__(16) float s_dp[LL];
  __shared__ __align__(16) float s_u[LL];
  __shared__ float smP[16][16];
  __shared__ float smS[16][64];
  int e = blockIdx.x, b = blockIdx.y;
  int t = threadIdx.x, w = t>>5, lane = t&31;
  int n = lane & 15, half = lane >> 4;
  int dX = half*2, dY = dX+1;
  float Ane = -__expf(A_log[e*Nn + n]);
  float dbx = dirB[dX*Nn + n];
  float dby = dirB[dY*Nn + n];
  float Dval = Dv[e];
  const int bL = b*LL;
  int l0 = w*256;

  // stage delta row + u row (16KB each) into smem
  {
    const float4* dpg = (const float4*)(g_delta + ((size_t)(b*Ee + e))*LL);
    const float4* ug  = (const float4*)(g_xpT  + ((size_t)(b*Ee + e))*LL);
    #pragma unroll
    for (int idx = t; idx < LL/4; idx += 512){
      ((float4*)s_dp)[idx] = dpg[idx];
      ((float4*)s_u)[idx]  = ug[idx];
    }
  }
  __syncthreads();

  const float* dp  = s_dp + l0;
  const float2* pBC = g_BC + ((size_t)(bL+l0))*Nn + n;
  const int2*  po  = g_ordp + half*LL + l0;

  if (w < 15){
    float P = 1.f, sx = 0.f, sy = 0.f;
    #pragma unroll 4
    for (int k=0;k<256;++k){
      float delta = dp[k];
      float Bv = pBC[(size_t)k*Nn].x;
      int2 oo = po[k];
      float ux = s_u[oo.x];
      float uy = s_u[oo.y];
      float dA = __expf(delta*Ane);
      float dB = delta*Bv;
      sx = dA*sx + (dB + delta*dbx)*ux;
      sy = dA*sy + (dB + delta*dby)*uy;
      P *= dA;
    }
    if (half == 0) smP[w][n] = P;
    smS[w][dX*16+n] = sx;
    smS[w][dY*16+n] = sy;
  }
  __syncthreads();
  float hx = 0.f, hy = 0.f;
  for (int j=0;j<w;++j){
    float Pj = smP[j][n];
    hx = Pj*hx + smS[j][dX*16+n];
    hy = Pj*hy + smS[j][dY*16+n];
  }

  bool isY = (lane & 8) != 0;
  int dSel = dX + (isY ? 1 : 0);
  bool writer = ((lane & 7) == 0);
  #pragma unroll 4
  for (int k=0;k<256;++k){
    float delta = dp[k];
    float2 bc = pBC[(size_t)k*Nn];
    int2 oo = po[k];
    float ux = s_u[oo.x];
    float uy = s_u[oo.y];
    float dA = __expf(delta*Ane);
    float dB = delta*bc.x;
    hx = dA*hx + (dB + delta*dbx)*ux;
    hy = dA*hy + (dB + delta*dby)*uy;
    float px = hx*bc.y, py = hy*bc.y;
    px += __shfl_xor_sync(0xffffffffu, px, 8);
    py += __shfl_xor_sync(0xffffffffu, py, 8);
    float z = isY ? py : px;
    z += __shfl_xor_sync(0xffffffffu, z, 4);
    z += __shfl_xor_sync(0xffffffffu, z, 2);
    z += __shfl_xor_sync(0xffffffffu, z, 1);
    if (writer){
      int o = isY ? oo.y : oo.x;
      float u = isY ? uy : ux;
      g_yd[((size_t)(bL + o)*Ee + e)*4 + dSel] = z + Dval*u;
    }
  }
}

// ---------------- local clustering (sums 4 fuse partials) ----------------
__global__ void k_cluster(const float* __restrict__ fw, const float* __restrict__ fb,
                          const float* __restrict__ vw, const float* __restrict__ vb,
                          const float* __restrict__ pw, const float* __restrict__ pb,
                          const float* __restrict__ salpha, const float* __restrict__ sbeta){
  __shared__ float xw[96][64];
  __shared__ float fsh[6][64], vsh[6][64];
  __shared__ float cen[6][25], vc[6][25];
  __shared__ float cnorm[25], fnorm[64];
  __shared__ float ssim[25][64];
  __shared__ int   kidx[64];
  __shared__ float sval[64];
  __shared__ float rowsum[25];
  __shared__ float agg[25][6];
  __shared__ float outw[6][64];

  int wi = blockIdx.x;
  int b = wi >> 6, Wg = (wi >> 3) & 7, Hg = wi & 7;
  int t = threadIdx.x;   // 128
  const size_t PS = (size_t)Bb*Cc*LL;

  for (int idx=t; idx<96*64; idx+=128){
    int c=idx>>6, pp=idx&63;
    int i = Wg*8 + (pp>>3), j = Hg*8 + (pp&7);
    size_t off = (size_t)(b*Cc+c)*LL + i*Ww + j;
    xw[c][pp] = (g_fpart[off] + g_fpart[off+PS]) + (g_fpart[off+2*PS] + g_fpart[off+3*PS]);
  }
  __syncthreads();
  for (int idx=t; idx<2*6*64; idx+=128){
    int which = idx/384; int r = idx%384;
    int o = r>>6, pp = r&63;
    if (!which){
      float a = fb[o];
      for (int c=0;c<48;c++) a += fw[o*48+c]*xw[c][pp];
      fsh[o][pp] = a;
    } else {
      float a = vb[o];
      for (int c=0;c<48;c++) a += vw[o*48+c]*xw[48+c][pp];
      vsh[o][pp] = a;
    }
  }
  __syncthreads();
  for (int idx=t; idx<2*6*25; idx+=128){
    int which = idx/150; int r = idx%150;
    int o = r/25, k = r%25;
    int ii = k/5, jj = k%5;
    int si=(ii*8)/5, ei=((ii+1)*8+4)/5, sj=(jj*8)/5, ej=((jj+1)*8+4)/5;
    float s = 0.f;
    for (int iw=si; iw<ei; iw++)
      for (int ih=sj; ih<ej; ih++)
        s += (which ? vsh[o][iw*8+ih] : fsh[o][iw*8+ih]);
    s /= (float)((ei-si)*(ej-sj));
    if (which) vc[o][k]=s; else cen[o][k]=s;
  }
  __syncthreads();
  if (t < 25){
    float s=0.f;
    for (int o=0;o<6;o++){ float v=cen[o][t]; s+=v*v; }
    cnorm[t] = fmaxf(sqrtf(s), 1e-12f);
  } else if (t >= 64 && t < 128){
    int pp = t-64;
    float s=0.f;
    for (int o=0;o<6;o++){ float v=fsh[o][pp]; s+=v*v; }
    fnorm[pp] = fmaxf(sqrtf(s), 1e-12f);
  }
  __syncthreads();
  float alpha = salpha[0], beta = sbeta[0];
  for (int idx=t; idx<25*64; idx+=128){
    int k = idx/64, pp = idx%64;
    float dp = 0.f;
    for (int o=0;o<6;o++) dp += cen[o][k]*fsh[o][pp];
    float xarg = beta + alpha*dp/(cnorm[k]*fnorm[pp]);
    ssim[k][pp] = 1.f/(1.f + expf(-xarg));
  }
  __syncthreads();
  if (t < 64){
    float best = -1e30f; int bk = 0;
    for (int k=0;k<25;k++){ float s = ssim[k][t]; if (s > best){ best = s; bk = k; } }
    kidx[t] = bk; sval[t] = best;
  }
  __syncthreads();
  if (t < 25){
    float rs = 0.f;
    for (int p=0;p<64;p++) if (kidx[p]==t) rs += sval[p];
    rowsum[t] = rs;
  }
  __syncthreads();
  for (int idx=t; idx<25*6; idx+=128){
    int k = idx/6, c = idx%6;
    float s = 0.f;
    for (int p=0;p<64;p++) if (kidx[p]==k) s += sval[p]*vsh[c][p];
    agg[k][c] = (s + vc[c][k]) / (rowsum[k] + 1.f);
  }
  __syncthreads();
  for (int idx=t; idx<6*64; idx+=128){
    int c = idx/64, p = idx%64;
    outw[c][p] = agg[kidx[p]][c]*sval[p];
  }
  __syncthreads();
  for (int idx=t; idx<96*64; idx+=128){
    int o = idx>>6, p = idx&63;
    float a = pb[o];
    #pragma unroll
    for (int c=0;c<6;c++) a += pw[o*6+c]*outw[c][p];
    int i = Wg*8+(p>>3), j = Hg*8+(p&7);
    g_clC[(size_t)(b*Cc+o)*LL + i*Ww+j] = a;
  }
}

// ---------------- cluster_proj (FFMA2, dup weights) ----------------
__global__ void k_clproj(const float* __restrict__ cpb){
  __shared__ __align__(16) float sx[96][16];
  int l0 = blockIdx.x*16; int b = blockIdx.y;
  int t = threadIdx.x;  // 192
  for (int idx=t; idx<96*16; idx+=192){
    int c=idx>>4, pp=idx&15;
    sx[c][pp] = g_clC[(size_t)(b*Cc+c)*LL + l0+pp];
  }
  __syncthreads();
  float bi = cpb[t];
  unsigned long long acc[8];
  unsigned long long bp = pack2(bi, bi);
  #pragma unroll
  for (int p=0;p<8;p++) acc[p]=bp;
  const unsigned long long* wrow = (const unsigned long long*)g_WtCl2 + t;
  for (int c=0;c<96;++c){
    unsigned long long wd = wrow[c*192];
    const ulonglong2* r = (const ulonglong2*)sx[c];
    ulonglong2 v0=r[0], v1=r[1];
    acc[0]=ffma2(wd,v0.x,acc[0]); acc[1]=ffma2(wd,v0.y,acc[1]);
    acc[2]=ffma2(wd,v1.x,acc[2]); acc[3]=ffma2(wd,v1.y,acc[3]);
    ulonglong2 v2=r[2], v3=r[3];
    acc[4]=ffma2(wd,v2.x,acc[4]); acc[5]=ffma2(wd,v2.y,acc[5]);
    acc[6]=ffma2(wd,v3.x,acc[6]); acc[7]=ffma2(wd,v3.y,acc[7]);
  }
  float y[16];
  #pragma unroll
  for (int p=0;p<8;p++) unpack2(acc[p], y[2*p], y[2*p+1]);
  #pragma unroll
  for (int p=0;p<16;++p)
    g_cl[((size_t)b*LL + l0+p)*Ee + t] = y[p];
}

// ---------------- LN mix + out_proj ----------------
__global__ void k_mix(const float* __restrict__ lnw, const float* __restrict__ lnb,
                      const float* __restrict__ bch, float* __restrict__ out){
  int b = blockIdx.y; int l0 = blockIdx.x*8;
  int t = threadIdx.x;  // 256
  int w = t>>5, lane = t&31;
  __shared__ __align__(16) float sy[192][12];
  __shared__ float sw0[192], sw1[192], sw2[192], slw[192], slb[192];
  if (t < 192){
    float b0 = bch[t], b1 = bch[192+t], b2 = bch[384+t];
    float mx = fmaxf(b0, fmaxf(b1,b2));
    float e0=__expf(b0-mx), e1=__expf(b1-mx), e2=__expf(b2-mx);
    float inv = 1.f/(e0+e1+e2);
    sw0[t]=e0*inv; sw1[t]=e1*inv; sw2[t]=e2*inv;
    slw[t]=lnw[t]; slb[t]=lnb[t];
  }
  __syncthreads();
  int l = l0 + w;
  size_t base = ((size_t)(b*LL + l))*Ee + lane;
  float ys[6], zv[6], cv[6];
  #pragma unroll
  for (int i=0;i<6;i++){
    float4 yv = *(const float4*)&g_yd[(base + 32*i)*4];
    ys[i] = (yv.x + yv.y) + (yv.z + yv.w);
    zv[i] = g_zp[base + 32*i];
    cv[i] = g_cl[base + 32*i];
  }
  float s1=0,q1=0,s2=0,q2=0,s3=0,q3=0;
  #pragma unroll
  for (int i=0;i<6;i++){
    s1+=ys[i]; q1+=ys[i]*ys[i];
    s2+=zv[i]; q2+=zv[i]*zv[i];
    s3+=cv[i]; q3+=cv[i]*cv[i];
  }
  #pragma unroll
  for (int m=16;m;m>>=1){
    s1 += __shfl_xor_sync(0xffffffffu, s1, m);
    q1 += __shfl_xor_sync(0xffffffffu, q1, m);
    s2 += __shfl_xor_sync(0xffffffffu, s2, m);
    q2 += __shfl_xor_sync(0xffffffffu, q2, m);
    s3 += __shfl_xor_sync(0xffffffffu, s3, m);
    q3 += __shfl_xor_sync(0xffffffffu, q3, m);
  }
  const float iE = 1.f/192.f;
  float m1=s1*iE, v1=q1*iE-m1*m1;
  float m2=s2*iE, v2=q2*iE-m2*m2;
  float m3=s3*iE, v3=q3*iE-m3*m3;
  float r1=rsqrtf(v1+1e-5f), r2=rsqrtf(v2+1e-5f), r3=rsqrtf(v3+1e-5f);
  #pragma unroll
  for (int i=0;i<6;i++){
    int e = lane + 32*i;
    float lwv = slw[e], lbv = slb[e];
    float ln1=(ys[i]-m1)*r1*lwv+lbv;
    float ln2=(zv[i]-m2)*r2*lwv+lbv;
    float ln3=(cv[i]-m3)*r3*lwv+lbv;
    sy[e][w] = sw0[e]*ln1 + sw1[e]*ln2 + sw2[e]*ln3;
  }
  __syncthreads();
  if (t < 192){
    int o = t%96, hf = t/96;
    const unsigned long long* w2 = (const unsigned long long*)g_WtOut2 + o;
    unsigned long long a01=0ull, a23=0ull;
    for (int e=0;e<192;e++){
      unsigned long long wp = w2[e*96];
      float4 v = *(const float4*)&sy[e][hf*4];
      a01 = ffma2(wp, pack2(v.x, v.y), a01);
      a23 = ffma2(wp, pack2(v.z, v.w), a23);
    }
    float o0,o1,o2,o3;
    unpack2(a01, o0, o1);
    unpack2(a23, o2, o3);
    out[((size_t)(b*LL + l0+hf*4+0))*Cc + o] = o0;
    out[((size_t)(b*LL + l0+hf*4+1))*Cc + o] = o1;
    out[((size_t)(b*LL + l0+hf*4+2))*Cc + o] = o2;
    out[((size_t)(b*LL + l0+hf*4+3))*Cc + o] = o3;
  }
}

extern "C" void kernel_launch(void* const* d_in, const int* in_sizes, int n_in,
                              void* d_out, int out_size){
  const float* x    = (const float*)d_in[0];
  const float* wh   = (const float*)d_in[3];
  const float* wv   = (const float*)d_in[4];
  const float* wd1  = (const float*)d_in[5];
  const float* wd2  = (const float*)d_in[6];
  const float* fw   = (const float*)d_in[7];
  const float* inw  = (const float*)d_in[8];
  const float* xpw  = (const float*)d_in[9];
  const float* dtw  = (const float*)d_in[10];
  const float* dtb  = (const float*)d_in[11];
  const float* alog = (const float*)d_in[12];
  const float* Dv   = (const float*)d_in[13];
  const float* dirB = (const float*)d_in[14];
  const float* opw  = (const float*)d_in[15];
  const float* sal  = (const float*)d_in[16];
  const float* sbe  = (const float*)d_in[17];
  const float* f_w  = (const float*)d_in[18];
  const float* f_b  = (const float*)d_in[19];
  const float* v_w  = (const float*)d_in[20];
  const float* v_b  = (const float*)d_in[21];
  const float* p_w  = (const float*)d_in[22];
  const float* p_b  = (const float*)d_in[23];
  const float* cpb  = (const float*)d_in[25];
  const float* bch  = (const float*)d_in[26];
  const float* lnw  = (const float*)d_in[27];
  const float* lnb  = (const float*)d_in[28];
  float* out = (float*)d_out;

  k_prep<<<592, 256>>>(inw, (const float*)d_in[24], opw, fw);
  k_transpose<<<dim3(LL/32, Cc/32, Bb), dim3(32,8)>>>(x);
  k_conv<<<dim3(4, Cc, Bb), 256>>>(wh, wv, wd1, wd2);
  k_fuse<<<dim3(LL/64, Bb, 8), 192>>>();
  k_inxp<<<dim3(LL/16, Bb), 384>>>(xpw, dtw, dtb);
  k_scan<<<dim3(Ee, Bb), 512>>>(alog, dirB, Dv);
  k_cluster<<<Bb*64, 128>>>(f_w, f_b, v_w, v_b, p_w, p_b, sal, sbe);
  k_clproj<<<dim3(LL/16, Bb), 192>>>(cpb);
  k_mix<<<dim3(LL/8, Bb), 256>>>(lnw, lnb, bch, out);
}